// round 3
// baseline (speedup 1.0000x reference)
#include <cuda_runtime.h>
#include <cuda_bf16.h>
#include <math.h>

#define DD 128              // feature dim (D == H == 128)
#define NMAX 50000
#define SWS 132             // smem W row stride (floats): 132*4=528 bytes, 16B-multiple

// ---------------- scratch (static device globals; no allocation) ----------------
__device__ __align__(16) float g_bufA[(size_t)NMAX * DD];   // h / rep / recon
__device__ __align__(16) float g_bufB[(size_t)NMAX * DD];   // agg (scatter target)
__device__ __align__(16) float g_x[(size_t)NMAX * DD];      // aligned copy of x
__device__ __align__(16) float g_token[DD];                 // aligned copy of mask token
__device__ float g_cnt_out[NMAX];
__device__ float g_cnt_in[NMAX];
__device__ float g_rs_out[NMAX];
__device__ float g_rs_in[NMAX];
__device__ int   g_maskflag[NMAX];

// ---------------- small setup kernels ----------------
__global__ void k_copy(const float* __restrict__ src, float* __restrict__ dst, int n) {
    int i = blockIdx.x * blockDim.x + threadIdx.x;
    if (i < n) dst[i] = src[i];     // scalar coalesced: alignment-safe
}

__global__ void k_init(float* __restrict__ cnt_out, float* __restrict__ cnt_in,
                       int* __restrict__ maskflag, float* __restrict__ out, int n) {
    int i = blockIdx.x * blockDim.x + threadIdx.x;
    if (i < n) { cnt_out[i] = 0.f; cnt_in[i] = 0.f; maskflag[i] = 0; }
    if (i == 0) out[0] = 0.f;
}

__global__ void k_mark(const int* __restrict__ mask_nodes, int* __restrict__ maskflag, int m) {
    int i = blockIdx.x * blockDim.x + threadIdx.x;
    if (i < m) maskflag[mask_nodes[i]] = 1;
}

__global__ void k_deg(const int* __restrict__ src, const int* __restrict__ dst,
                      float* __restrict__ co, float* __restrict__ ci, int e) {
    int i = blockIdx.x * blockDim.x + threadIdx.x;
    if (i < e) {
        atomicAdd(&co[src[i]], 1.f);
        atomicAdd(&ci[dst[i]], 1.f);
    }
}

__global__ void k_rsqrt(const float* __restrict__ co, const float* __restrict__ ci,
                        float* __restrict__ ro, float* __restrict__ ri, int n) {
    int i = blockIdx.x * blockDim.x + threadIdx.x;
    if (i < n) {
        ro[i] = rsqrtf(fmaxf(co[i], 1.f));
        ri[i] = rsqrtf(fmaxf(ci[i], 1.f));
    }
}

__global__ void k_zero(float4* __restrict__ p, int n4) {
    int i = blockIdx.x * blockDim.x + threadIdx.x;
    if (i < n4) p[i] = make_float4(0.f, 0.f, 0.f, 0.f);
}

// ---------------- scatter-aggregate: agg[dst] += feat[src] * rs_out[src] ----------------
// one warp per edge; each lane handles 4 contiguous floats (float4) of the 128-wide row.
// All pointers here are OUR aligned globals.
__global__ void __launch_bounds__(256)
k_scatter(const float* __restrict__ feat,     // used when use_mask_input == 0
          const float* __restrict__ x,        // aligned copy, used when use_mask_input == 1
          const float* __restrict__ token,    // aligned copy of mask token row
          const int* __restrict__ maskflag,
          const float* __restrict__ rs_out,
          const int* __restrict__ src, const int* __restrict__ dst,
          float* __restrict__ agg, int E, int use_mask_input) {
    int t = blockIdx.x * blockDim.x + threadIdx.x;
    int e = t >> 5;
    int lane = t & 31;
    if (e >= E) return;
    int s = src[e];
    int d = dst[e];
    float r = rs_out[s];
    float4 v;
    if (use_mask_input) {
        if (maskflag[s]) v = ((const float4*)token)[lane];
        else             v = ((const float4*)x)[(size_t)s * 32 + lane];
    } else {
        v = ((const float4*)feat)[(size_t)s * 32 + lane];
    }
    v.x *= r; v.y *= r; v.z *= r; v.w *= r;
    float* a = agg + ((size_t)d * DD + lane * 4);
    asm volatile("red.global.add.v4.f32 [%0], {%1,%2,%3,%4};"
                 :: "l"(a), "f"(v.x), "f"(v.y), "f"(v.z), "f"(v.w)
                 : "memory");
}

// ---------------- fused GEMM (out = in @ W^T [+ bias]) + epilogue ----------------
// mode 0: rst = (in@W^T + b) * rs_in  -> LayerNorm(g,be) -> PReLU(a)       (encoder layers)
// mode 1: out = (in@W^T + b) * rs_in                                        (decoder conv)
// mode 2: out = in@W^T (no bias), then zero masked rows; in==out allowed    (enc->dec + re-mask)
// block: 512 threads, 64 rows x 128 cols tile; thread = 4 rows x 4 cols.
// each warp (fixed ty) owns 4 complete rows -> LayerNorm via warp shuffles.
// W / bias / gamma / beta / alpha are EXTERNAL pointers: scalar loads only.
__global__ void __launch_bounds__(512, 2)
k_gemm(const float* __restrict__ in, float* __restrict__ out,
       const float* __restrict__ W, const float* __restrict__ bias,
       const float* __restrict__ rs_in,
       const float* __restrict__ gamma, const float* __restrict__ beta,
       const float* __restrict__ alpha,
       const int* __restrict__ maskflag,
       int n, int mode) {
    extern __shared__ float sm[];
    float* sW = sm;                 // [128][SWS] transposed W: sW[k*SWS + c] = W[c*128 + k]
    float* sA = sm + 128 * SWS;    // [64][128] input tile

    const int tid  = threadIdx.x;
    const int row0 = blockIdx.x * 64;

    // load W transposed (scalar coalesced: W may be only 4B-aligned)
    #pragma unroll
    for (int i = tid; i < 128 * 128; i += 512) {
        int c = i >> 7;        // output col
        int k = i & 127;       // k index
        sW[k * SWS + c] = W[i];
    }
    // load input tile (our aligned buffers -> float4 ok)
    int rows = n - row0; if (rows > 64) rows = 64;
    #pragma unroll
    for (int i = tid; i < 64 * 32; i += 512) {
        int r = i >> 5, c4 = i & 31;
        float4 v = (r < rows) ? ((const float4*)in)[(size_t)(row0 + r) * 32 + c4]
                              : make_float4(0.f, 0.f, 0.f, 0.f);
        ((float4*)sA)[i] = v;
    }
    __syncthreads();

    const int tx = tid & 31;        // col group
    const int ty = tid >> 5;        // warp id -> row group
    const int c0 = tx * 4;
    const int r0 = ty * 4;

    float acc[4][4];
    #pragma unroll
    for (int i = 0; i < 4; i++)
        #pragma unroll
        for (int j = 0; j < 4; j++) acc[i][j] = 0.f;

    #pragma unroll 8
    for (int k = 0; k < 128; k++) {
        // SWS=132 -> (k*132 + c0) % 4 == 0 -> 16B-aligned v4 smem load, always legal
        float4 w = *(const float4*)&sW[k * SWS + c0];
        float a0 = sA[(r0 + 0) * 128 + k];
        float a1 = sA[(r0 + 1) * 128 + k];
        float a2 = sA[(r0 + 2) * 128 + k];
        float a3 = sA[(r0 + 3) * 128 + k];
        acc[0][0] += a0 * w.x; acc[0][1] += a0 * w.y; acc[0][2] += a0 * w.z; acc[0][3] += a0 * w.w;
        acc[1][0] += a1 * w.x; acc[1][1] += a1 * w.y; acc[1][2] += a1 * w.z; acc[1][3] += a1 * w.w;
        acc[2][0] += a2 * w.x; acc[2][1] += a2 * w.y; acc[2][2] += a2 * w.z; acc[2][3] += a2 * w.w;
        acc[3][0] += a3 * w.x; acc[3][1] += a3 * w.y; acc[3][2] += a3 * w.z; acc[3][3] += a3 * w.w;
    }

    // epilogue (scalar loads from external param pointers)
    float aP = (mode == 0) ? alpha[0] : 0.f;
    float b0 = 0.f, b1v = 0.f, b2v = 0.f, b3 = 0.f;
    float gx = 0.f, gy = 0.f, gz = 0.f, gw_ = 0.f;
    float ex = 0.f, ey = 0.f, ez = 0.f, ew = 0.f;
    if (mode != 2) {
        b0 = bias[c0 + 0]; b1v = bias[c0 + 1]; b2v = bias[c0 + 2]; b3 = bias[c0 + 3];
    }
    if (mode == 0) {
        gx = gamma[c0 + 0]; gy = gamma[c0 + 1]; gz = gamma[c0 + 2]; gw_ = gamma[c0 + 3];
        ex = beta[c0 + 0];  ey = beta[c0 + 1];  ez = beta[c0 + 2];  ew = beta[c0 + 3];
    }
    #pragma unroll
    for (int i = 0; i < 4; i++) {
        int row = row0 + r0 + i;
        if (row >= n) continue;                 // warp-uniform
        float4 o4;
        if (mode == 2) {
            if (maskflag[row]) {
                o4 = make_float4(0.f, 0.f, 0.f, 0.f);
            } else {
                o4 = make_float4(acc[i][0], acc[i][1], acc[i][2], acc[i][3]);
            }
        } else {
            float rs = rs_in[row];
            float v0 = (acc[i][0] + b0)  * rs;
            float v1 = (acc[i][1] + b1v) * rs;
            float v2 = (acc[i][2] + b2v) * rs;
            float v3 = (acc[i][3] + b3)  * rs;
            if (mode == 0) {
                float s  = v0 + v1 + v2 + v3;
                float ss = v0 * v0 + v1 * v1 + v2 * v2 + v3 * v3;
                #pragma unroll
                for (int o = 16; o; o >>= 1) {
                    s  += __shfl_xor_sync(0xffffffffu, s,  o);
                    ss += __shfl_xor_sync(0xffffffffu, ss, o);
                }
                float mu  = s * (1.f / 128.f);
                float var = ss * (1.f / 128.f) - mu * mu;
                float inv = rsqrtf(var + 1e-5f);
                float y0 = (v0 - mu) * inv * gx  + ex; y0 = (y0 >= 0.f) ? y0 : aP * y0;
                float y1 = (v1 - mu) * inv * gy  + ey; y1 = (y1 >= 0.f) ? y1 : aP * y1;
                float y2 = (v2 - mu) * inv * gz  + ez; y2 = (y2 >= 0.f) ? y2 : aP * y2;
                float y3 = (v3 - mu) * inv * gw_ + ew; y3 = (y3 >= 0.f) ? y3 : aP * y3;
                o4 = make_float4(y0, y1, y2, y3);
            } else {
                o4 = make_float4(v0, v1, v2, v3);
            }
        }
        ((float4*)out)[(size_t)row * 32 + tx] = o4;   // out is our aligned buffer
    }
}

// ---------------- SCE loss over masked rows ----------------
// recon and x are OUR aligned buffers (g_bufA, g_x).
__global__ void __launch_bounds__(256)
k_loss(const float* __restrict__ recon, const float* __restrict__ x,
       const int* __restrict__ mask_nodes, int m, float* __restrict__ out) {
    __shared__ float part[8];
    int gw   = (blockIdx.x * blockDim.x + threadIdx.x) >> 5;
    int lane = threadIdx.x & 31;
    int wl   = threadIdx.x >> 5;
    float term = 0.f;
    if (gw < m) {
        int node = mask_nodes[gw];
        float4 r  = ((const float4*)recon)[(size_t)node * 32 + lane];
        float4 xv = ((const float4*)x)[(size_t)node * 32 + lane];
        float dot = r.x * xv.x + r.y * xv.y + r.z * xv.z + r.w * xv.w;
        float nr  = r.x * r.x + r.y * r.y + r.z * r.z + r.w * r.w;
        float nx  = xv.x * xv.x + xv.y * xv.y + xv.z * xv.z + xv.w * xv.w;
        #pragma unroll
        for (int o = 16; o; o >>= 1) {
            dot += __shfl_xor_sync(0xffffffffu, dot, o);
            nr  += __shfl_xor_sync(0xffffffffu, nr,  o);
            nx  += __shfl_xor_sync(0xffffffffu, nx,  o);
        }
        if (lane == 0) {
            float c = dot / (fmaxf(sqrtf(nr), 1e-12f) * fmaxf(sqrtf(nx), 1e-12f));
            float t = 1.f - c;
            term = t * t;
        }
    }
    if (lane == 0) part[wl] = term;
    __syncthreads();
    if (threadIdx.x == 0) {
        float s = 0.f;
        #pragma unroll
        for (int i = 0; i < 8; i++) s += part[i];
        atomicAdd(out, s / (float)m);
    }
}

// ---------------- launch ----------------
extern "C" void kernel_launch(void* const* d_in, const int* in_sizes, int n_in,
                              void* d_out, int out_size) {
    const float* x     = (const float*)d_in[0];
    const float* token = (const float*)d_in[1];
    const float* W1    = (const float*)d_in[2];
    const float* b1    = (const float*)d_in[3];
    const float* g1    = (const float*)d_in[4];
    const float* be1   = (const float*)d_in[5];
    const float* a1    = (const float*)d_in[6];
    const float* W2    = (const float*)d_in[7];
    const float* b2    = (const float*)d_in[8];
    const float* g2    = (const float*)d_in[9];
    const float* be2   = (const float*)d_in[10];
    const float* a2    = (const float*)d_in[11];
    const float* We2d  = (const float*)d_in[12];
    const float* Wd    = (const float*)d_in[13];
    const float* bd    = (const float*)d_in[14];
    const int*   src   = (const int*)d_in[15];
    const int*   dst   = (const int*)d_in[16];
    const int*   mask  = (const int*)d_in[17];

    const int n = in_sizes[0] / DD;
    const int E = in_sizes[15];
    const int M = in_sizes[17];
    float* out = (float*)d_out;

    float *bufA, *bufB, *xA, *tokA, *cnt_out, *cnt_in, *rs_out, *rs_in;
    int* maskflag;
    cudaGetSymbolAddress((void**)&bufA, g_bufA);
    cudaGetSymbolAddress((void**)&bufB, g_bufB);
    cudaGetSymbolAddress((void**)&xA,   g_x);
    cudaGetSymbolAddress((void**)&tokA, g_token);
    cudaGetSymbolAddress((void**)&cnt_out, g_cnt_out);
    cudaGetSymbolAddress((void**)&cnt_in, g_cnt_in);
    cudaGetSymbolAddress((void**)&rs_out, g_rs_out);
    cudaGetSymbolAddress((void**)&rs_in, g_rs_in);
    cudaGetSymbolAddress((void**)&maskflag, g_maskflag);

    const size_t smem = (128 * SWS + 64 * 128) * sizeof(float);   // 100352 B
    cudaFuncSetAttribute(k_gemm, cudaFuncAttributeMaxDynamicSharedMemorySize, (int)smem);

    const int T = 256;
    const int gN = (n + T - 1) / T;
    const int gE = (E + T - 1) / T;
    const int gS = ((E * 32) + T - 1) / T;          // scatter: warp per edge
    const int n4 = (n * DD) / 4;
    const int gZ = (n4 + T - 1) / T;
    const int gG = (n + 63) / 64;
    const int gL = ((M * 32) + T - 1) / T;
    const int nd = n * DD;

    // aligned copies of external float tensors we access with wide ops
    k_copy <<<(nd + T - 1) / T, T>>>(x, xA, nd);
    k_copy <<<1, DD>>>(token, tokA, DD);

    // setup: degrees, mask flags, rsqrt norms, zero output
    k_init <<<gN, T>>>(cnt_out, cnt_in, maskflag, out, n);
    k_mark <<<(M + T - 1) / T, T>>>(mask, maskflag, M);
    k_deg  <<<gE, T>>>(src, dst, cnt_out, cnt_in, E);
    k_rsqrt<<<gN, T>>>(cnt_out, cnt_in, rs_out, rs_in, n);

    // ---- conv1: use_x (masked x) -> agg -> GEMM+LN+PReLU -> bufA
    k_zero   <<<gZ, T>>>((float4*)bufB, n4);
    k_scatter<<<gS, T>>>(nullptr, xA, tokA, maskflag, rs_out, src, dst, bufB, E, 1);
    k_gemm   <<<gG, 512, smem>>>(bufB, bufA, W1, b1, rs_in, g1, be1, a1, maskflag, n, 0);

    // ---- conv2: bufA -> agg -> GEMM+LN+PReLU -> bufA
    k_zero   <<<gZ, T>>>((float4*)bufB, n4);
    k_scatter<<<gS, T>>>(bufA, nullptr, tokA, maskflag, rs_out, src, dst, bufB, E, 0);
    k_gemm   <<<gG, 512, smem>>>(bufB, bufA, W2, b2, rs_in, g2, be2, a2, maskflag, n, 0);

    // ---- encoder_to_decoder + re-mask (in-place, row-local)
    k_gemm   <<<gG, 512, smem>>>(bufA, bufA, We2d, bd, rs_in, g2, be2, a2, maskflag, n, 2);

    // ---- decoder conv: rep(bufA) -> agg -> GEMM (bias + deg scale) -> bufA = recon
    k_zero   <<<gZ, T>>>((float4*)bufB, n4);
    k_scatter<<<gS, T>>>(bufA, nullptr, tokA, maskflag, rs_out, src, dst, bufB, E, 0);
    k_gemm   <<<gG, 512, smem>>>(bufB, bufA, Wd, bd, rs_in, g2, be2, a2, maskflag, n, 1);

    // ---- SCE loss on masked rows
    k_loss   <<<gL, T>>>(bufA, x, mask, M, out);
}

// round 4
// speedup vs baseline: 1.2307x; 1.2307x over previous
#include <cuda_runtime.h>
#include <cuda_bf16.h>
#include <math.h>

#define DD 128              // feature dim (D == H == 128)
#define NMAX 50000
#define EMAX 800000
#define SWS 132             // smem W row stride (floats): 528 bytes, 16B-multiple

// ---------------- scratch (static device globals; no allocation) ----------------
__device__ __align__(16) float g_bufA[(size_t)NMAX * DD];   // h / rep / recon
__device__ __align__(16) float g_bufB[(size_t)NMAX * DD];   // agg target
__device__ __align__(16) float g_x[(size_t)NMAX * DD];      // aligned copy of x
__device__ __align__(16) float g_token[DD];                 // aligned copy of mask token
__device__ int   g_deg_out[NMAX];
__device__ int   g_deg_in[NMAX];
__device__ float g_rs_out[NMAX];
__device__ float g_rs_in[NMAX];
__device__ int   g_maskflag[NMAX];
__device__ int   g_rowptr[NMAX + 1];
__device__ int   g_fill[NMAX];
__device__ int   g_csrc[EMAX];      // CSR (by dst) source-node list

// ---------------- small setup kernels ----------------
__global__ void k_copy(const float* __restrict__ src, float* __restrict__ dst, int n) {
    int i = blockIdx.x * blockDim.x + threadIdx.x;
    if (i < n) dst[i] = src[i];     // scalar coalesced: alignment-safe
}

__global__ void k_init(int* __restrict__ deg_out, int* __restrict__ deg_in,
                       int* __restrict__ fill, int* __restrict__ maskflag,
                       float* __restrict__ out, int n) {
    int i = blockIdx.x * blockDim.x + threadIdx.x;
    if (i < n) { deg_out[i] = 0; deg_in[i] = 0; fill[i] = 0; maskflag[i] = 0; }
    if (i == 0) out[0] = 0.f;
}

__global__ void k_mark(const int* __restrict__ mask_nodes, int* __restrict__ maskflag, int m) {
    int i = blockIdx.x * blockDim.x + threadIdx.x;
    if (i < m) maskflag[mask_nodes[i]] = 1;
}

__global__ void k_deg(const int* __restrict__ src, const int* __restrict__ dst,
                      int* __restrict__ dout, int* __restrict__ din, int e) {
    int i = blockIdx.x * blockDim.x + threadIdx.x;
    if (i < e) {
        atomicAdd(&dout[src[i]], 1);
        atomicAdd(&din[dst[i]], 1);
    }
}

__global__ void k_rsqrt(const int* __restrict__ dout, const int* __restrict__ din,
                        float* __restrict__ ro, float* __restrict__ ri, int n) {
    int i = blockIdx.x * blockDim.x + threadIdx.x;
    if (i < n) {
        ro[i] = rsqrtf(fmaxf((float)dout[i], 1.f));
        ri[i] = rsqrtf(fmaxf((float)din[i], 1.f));
    }
}

// ---------------- exclusive scan of in-degrees -> rowptr (single block) ----------------
__global__ void __launch_bounds__(1024)
k_scan(const int* __restrict__ deg, int* __restrict__ rowptr, int n) {
    __shared__ int part[1024];
    int t = threadIdx.x;
    int chunk = (n + 1023) / 1024;
    int lo = t * chunk;
    int hi = lo + chunk; if (hi > n) hi = n; if (lo > n) lo = n;
    int s = 0;
    for (int i = lo; i < hi; i++) s += deg[i];
    part[t] = s;
    __syncthreads();
    // inclusive Hillis-Steele scan
    for (int o = 1; o < 1024; o <<= 1) {
        int v = (t >= o) ? part[t - o] : 0;
        __syncthreads();
        part[t] += v;
        __syncthreads();
    }
    int base = (t == 0) ? 0 : part[t - 1];
    for (int i = lo; i < hi; i++) {
        rowptr[i] = base;
        base += deg[i];
    }
    if (t == 1023) rowptr[n] = part[1023];
}

// ---------------- CSR fill: csrc[rowptr[dst]+k] = src ----------------
__global__ void k_fill(const int* __restrict__ src, const int* __restrict__ dst,
                       const int* __restrict__ rowptr, int* __restrict__ fill,
                       int* __restrict__ csrc, int e) {
    int i = blockIdx.x * blockDim.x + threadIdx.x;
    if (i < e) {
        int d = dst[i];
        int p = rowptr[d] + atomicAdd(&fill[d], 1);
        csrc[p] = src[i];
    }
}

// ---------------- CSR aggregation: agg[v] = sum_{s in in(v)} feat[s]*rs_out[s] ----------------
// one warp per node; each lane owns a float4 chunk of the 128-wide row; no atomics.
__global__ void __launch_bounds__(256)
k_agg(const float* __restrict__ feat,     // used when use_mask == 0
      const float* __restrict__ x,        // aligned x copy, used when use_mask == 1
      const float* __restrict__ token,
      const int* __restrict__ maskflag,
      const float* __restrict__ rs_out,
      const int* __restrict__ rowptr, const int* __restrict__ csrc,
      float* __restrict__ agg, int n, int use_mask) {
    int w = (blockIdx.x * blockDim.x + threadIdx.x) >> 5;
    int lane = threadIdx.x & 31;
    if (w >= n) return;
    int beg = rowptr[w];
    int end = rowptr[w + 1];
    float4 acc = make_float4(0.f, 0.f, 0.f, 0.f);
    float4 tok = make_float4(0.f, 0.f, 0.f, 0.f);
    if (use_mask) tok = ((const float4*)token)[lane];
    for (int e = beg; e < end; e++) {
        int s = csrc[e];                 // warp-broadcast load
        float r = rs_out[s];             // warp-broadcast load
        float4 v;
        if (use_mask && maskflag[s]) {
            v = tok;
        } else {
            const float4* base = (const float4*)(use_mask ? x : feat);
            v = base[(size_t)s * 32 + lane];
        }
        acc.x += r * v.x; acc.y += r * v.y; acc.z += r * v.z; acc.w += r * v.w;
    }
    ((float4*)agg)[(size_t)w * 32 + lane] = acc;
}

// ---------------- fused GEMM (out = in @ W^T [+ bias]) + epilogue ----------------
// mode 0: (in@W^T + b)*rs_in -> LayerNorm(g,be) -> PReLU(a)   (encoder layers)
// mode 1: (in@W^T + b)*rs_in                                   (decoder conv)
// mode 2: in@W^T, then zero masked rows; in==out allowed       (enc->dec + re-mask)
__global__ void __launch_bounds__(512, 2)
k_gemm(const float* __restrict__ in, float* __restrict__ out,
       const float* __restrict__ W, const float* __restrict__ bias,
       const float* __restrict__ rs_in,
       const float* __restrict__ gamma, const float* __restrict__ beta,
       const float* __restrict__ alpha,
       const int* __restrict__ maskflag,
       int n, int mode) {
    extern __shared__ float sm[];
    float* sW = sm;                 // [128][SWS] transposed W
    float* sA = sm + 128 * SWS;     // [64][128] input tile

    const int tid  = threadIdx.x;
    const int row0 = blockIdx.x * 64;

    #pragma unroll
    for (int i = tid; i < 128 * 128; i += 512) {
        int c = i >> 7;
        int k = i & 127;
        sW[k * SWS + c] = W[i];     // scalar coalesced (W may be 4B-aligned)
    }
    int rows = n - row0; if (rows > 64) rows = 64;
    #pragma unroll
    for (int i = tid; i < 64 * 32; i += 512) {
        int r = i >> 5, c4 = i & 31;
        float4 v = (r < rows) ? ((const float4*)in)[(size_t)(row0 + r) * 32 + c4]
                              : make_float4(0.f, 0.f, 0.f, 0.f);
        ((float4*)sA)[i] = v;
    }
    __syncthreads();

    const int tx = tid & 31;
    const int ty = tid >> 5;
    const int c0 = tx * 4;
    const int r0 = ty * 4;

    float acc[4][4];
    #pragma unroll
    for (int i = 0; i < 4; i++)
        #pragma unroll
        for (int j = 0; j < 4; j++) acc[i][j] = 0.f;

    #pragma unroll 8
    for (int k = 0; k < 128; k++) {
        float4 w = *(const float4*)&sW[k * SWS + c0];   // 16B-aligned (SWS%4==0)
        float a0 = sA[(r0 + 0) * 128 + k];
        float a1 = sA[(r0 + 1) * 128 + k];
        float a2 = sA[(r0 + 2) * 128 + k];
        float a3 = sA[(r0 + 3) * 128 + k];
        acc[0][0] += a0 * w.x; acc[0][1] += a0 * w.y; acc[0][2] += a0 * w.z; acc[0][3] += a0 * w.w;
        acc[1][0] += a1 * w.x; acc[1][1] += a1 * w.y; acc[1][2] += a1 * w.z; acc[1][3] += a1 * w.w;
        acc[2][0] += a2 * w.x; acc[2][1] += a2 * w.y; acc[2][2] += a2 * w.z; acc[2][3] += a2 * w.w;
        acc[3][0] += a3 * w.x; acc[3][1] += a3 * w.y; acc[3][2] += a3 * w.z; acc[3][3] += a3 * w.w;
    }

    float aP = (mode == 0) ? alpha[0] : 0.f;
    float b0 = 0.f, b1v = 0.f, b2v = 0.f, b3 = 0.f;
    float gx = 0.f, gy = 0.f, gz = 0.f, gw_ = 0.f;
    float ex = 0.f, ey = 0.f, ez = 0.f, ew = 0.f;
    if (mode != 2) {
        b0 = bias[c0 + 0]; b1v = bias[c0 + 1]; b2v = bias[c0 + 2]; b3 = bias[c0 + 3];
    }
    if (mode == 0) {
        gx = gamma[c0 + 0]; gy = gamma[c0 + 1]; gz = gamma[c0 + 2]; gw_ = gamma[c0 + 3];
        ex = beta[c0 + 0];  ey = beta[c0 + 1];  ez = beta[c0 + 2];  ew = beta[c0 + 3];
    }
    #pragma unroll
    for (int i = 0; i < 4; i++) {
        int row = row0 + r0 + i;
        if (row >= n) continue;
        float4 o4;
        if (mode == 2) {
            if (maskflag[row]) {
                o4 = make_float4(0.f, 0.f, 0.f, 0.f);
            } else {
                o4 = make_float4(acc[i][0], acc[i][1], acc[i][2], acc[i][3]);
            }
        } else {
            float rs = rs_in[row];
            float v0 = (acc[i][0] + b0)  * rs;
            float v1 = (acc[i][1] + b1v) * rs;
            float v2 = (acc[i][2] + b2v) * rs;
            float v3 = (acc[i][3] + b3)  * rs;
            if (mode == 0) {
                float s  = v0 + v1 + v2 + v3;
                float ss = v0 * v0 + v1 * v1 + v2 * v2 + v3 * v3;
                #pragma unroll
                for (int o = 16; o; o >>= 1) {
                    s  += __shfl_xor_sync(0xffffffffu, s,  o);
                    ss += __shfl_xor_sync(0xffffffffu, ss, o);
                }
                float mu  = s * (1.f / 128.f);
                float var = ss * (1.f / 128.f) - mu * mu;
                float inv = rsqrtf(var + 1e-5f);
                float y0 = (v0 - mu) * inv * gx  + ex; y0 = (y0 >= 0.f) ? y0 : aP * y0;
                float y1 = (v1 - mu) * inv * gy  + ey; y1 = (y1 >= 0.f) ? y1 : aP * y1;
                float y2 = (v2 - mu) * inv * gz  + ez; y2 = (y2 >= 0.f) ? y2 : aP * y2;
                float y3 = (v3 - mu) * inv * gw_ + ew; y3 = (y3 >= 0.f) ? y3 : aP * y3;
                o4 = make_float4(y0, y1, y2, y3);
            } else {
                o4 = make_float4(v0, v1, v2, v3);
            }
        }
        ((float4*)out)[(size_t)row * 32 + tx] = o4;
    }
}

// ---------------- SCE loss over masked rows ----------------
__global__ void __launch_bounds__(256)
k_loss(const float* __restrict__ recon, const float* __restrict__ x,
       const int* __restrict__ mask_nodes, int m, float* __restrict__ out) {
    __shared__ float part[8];
    int gw   = (blockIdx.x * blockDim.x + threadIdx.x) >> 5;
    int lane = threadIdx.x & 31;
    int wl   = threadIdx.x >> 5;
    float term = 0.f;
    if (gw < m) {
        int node = mask_nodes[gw];
        float4 r  = ((const float4*)recon)[(size_t)node * 32 + lane];
        float4 xv = ((const float4*)x)[(size_t)node * 32 + lane];
        float dot = r.x * xv.x + r.y * xv.y + r.z * xv.z + r.w * xv.w;
        float nr  = r.x * r.x + r.y * r.y + r.z * r.z + r.w * r.w;
        float nx  = xv.x * xv.x + xv.y * xv.y + xv.z * xv.z + xv.w * xv.w;
        #pragma unroll
        for (int o = 16; o; o >>= 1) {
            dot += __shfl_xor_sync(0xffffffffu, dot, o);
            nr  += __shfl_xor_sync(0xffffffffu, nr,  o);
            nx  += __shfl_xor_sync(0xffffffffu, nx,  o);
        }
        if (lane == 0) {
            float c = dot / (fmaxf(sqrtf(nr), 1e-12f) * fmaxf(sqrtf(nx), 1e-12f));
            float t = 1.f - c;
            term = t * t;
        }
    }
    if (lane == 0) part[wl] = term;
    __syncthreads();
    if (threadIdx.x == 0) {
        float s = 0.f;
        #pragma unroll
        for (int i = 0; i < 8; i++) s += part[i];
        atomicAdd(out, s / (float)m);
    }
}

// ---------------- launch ----------------
extern "C" void kernel_launch(void* const* d_in, const int* in_sizes, int n_in,
                              void* d_out, int out_size) {
    const float* x     = (const float*)d_in[0];
    const float* token = (const float*)d_in[1];
    const float* W1    = (const float*)d_in[2];
    const float* b1    = (const float*)d_in[3];
    const float* g1    = (const float*)d_in[4];
    const float* be1   = (const float*)d_in[5];
    const float* a1    = (const float*)d_in[6];
    const float* W2    = (const float*)d_in[7];
    const float* b2    = (const float*)d_in[8];
    const float* g2    = (const float*)d_in[9];
    const float* be2   = (const float*)d_in[10];
    const float* a2    = (const float*)d_in[11];
    const float* We2d  = (const float*)d_in[12];
    const float* Wd    = (const float*)d_in[13];
    const float* bd    = (const float*)d_in[14];
    const int*   src   = (const int*)d_in[15];
    const int*   dst   = (const int*)d_in[16];
    const int*   mask  = (const int*)d_in[17];

    const int n = in_sizes[0] / DD;
    const int E = in_sizes[15];
    const int M = in_sizes[17];
    float* out = (float*)d_out;

    float *bufA, *bufB, *xA, *tokA, *rs_out, *rs_in;
    int *deg_out, *deg_in, *maskflag, *rowptr, *fill, *csrc;
    cudaGetSymbolAddress((void**)&bufA, g_bufA);
    cudaGetSymbolAddress((void**)&bufB, g_bufB);
    cudaGetSymbolAddress((void**)&xA,   g_x);
    cudaGetSymbolAddress((void**)&tokA, g_token);
    cudaGetSymbolAddress((void**)&deg_out, g_deg_out);
    cudaGetSymbolAddress((void**)&deg_in,  g_deg_in);
    cudaGetSymbolAddress((void**)&rs_out, g_rs_out);
    cudaGetSymbolAddress((void**)&rs_in,  g_rs_in);
    cudaGetSymbolAddress((void**)&maskflag, g_maskflag);
    cudaGetSymbolAddress((void**)&rowptr, g_rowptr);
    cudaGetSymbolAddress((void**)&fill,   g_fill);
    cudaGetSymbolAddress((void**)&csrc,   g_csrc);

    const size_t smem = (128 * SWS + 64 * 128) * sizeof(float);   // 100352 B
    cudaFuncSetAttribute(k_gemm, cudaFuncAttributeMaxDynamicSharedMemorySize, (int)smem);

    const int T = 256;
    const int gN = (n + T - 1) / T;
    const int gE = (E + T - 1) / T;
    const int gA = ((n * 32) + T - 1) / T;          // agg: warp per node
    const int gG = (n + 63) / 64;
    const int gL = ((M * 32) + T - 1) / T;
    const int nd = n * DD;

    // aligned copies of external float tensors we access with wide ops
    k_copy <<<(nd + T - 1) / T, T>>>(x, xA, nd);
    k_copy <<<1, DD>>>(token, tokA, DD);

    // setup: degrees, mask flags, rsqrt norms, CSR build
    k_init <<<gN, T>>>(deg_out, deg_in, fill, maskflag, out, n);
    k_mark <<<(M + T - 1) / T, T>>>(mask, maskflag, M);
    k_deg  <<<gE, T>>>(src, dst, deg_out, deg_in, E);
    k_rsqrt<<<gN, T>>>(deg_out, deg_in, rs_out, rs_in, n);
    k_scan <<<1, 1024>>>(deg_in, rowptr, n);
    k_fill <<<gE, T>>>(src, dst, rowptr, fill, csrc, E);

    // ---- conv1: masked x -> agg -> GEMM+LN+PReLU -> bufA
    k_agg  <<<gA, T>>>(nullptr, xA, tokA, maskflag, rs_out, rowptr, csrc, bufB, n, 1);
    k_gemm <<<gG, 512, smem>>>(bufB, bufA, W1, b1, rs_in, g1, be1, a1, maskflag, n, 0);

    // ---- conv2: bufA -> agg -> GEMM+LN+PReLU -> bufA
    k_agg  <<<gA, T>>>(bufA, nullptr, tokA, maskflag, rs_out, rowptr, csrc, bufB, n, 0);
    k_gemm <<<gG, 512, smem>>>(bufB, bufA, W2, b2, rs_in, g2, be2, a2, maskflag, n, 0);

    // ---- encoder_to_decoder + re-mask (in-place, row-local)
    k_gemm <<<gG, 512, smem>>>(bufA, bufA, We2d, bd, rs_in, g2, be2, a2, maskflag, n, 2);

    // ---- decoder conv: rep(bufA) -> agg -> GEMM (bias + deg scale) -> bufA = recon
    k_agg  <<<gA, T>>>(bufA, nullptr, tokA, maskflag, rs_out, rowptr, csrc, bufB, n, 0);
    k_gemm <<<gG, 512, smem>>>(bufB, bufA, Wd, bd, rs_in, g2, be2, a2, maskflag, n, 1);

    // ---- SCE loss on masked rows
    k_loss <<<gL, T>>>(bufA, x, mask, M, out);
}

// round 5
// speedup vs baseline: 1.3958x; 1.1341x over previous
#include <cuda_runtime.h>
#include <cuda_fp16.h>
#include <math.h>

#define DD 128              // feature dim (D == H == 128)
#define NMAX 50000
#define EMAX 800000
#define SWS 132             // smem W row stride (floats): 528 bytes, 16B-multiple

// ---------------- scratch (static device globals; no allocation) ----------------
__device__ __align__(16) float  g_bufA[(size_t)NMAX * DD];   // h2 / recon (fp32)
__device__ __align__(16) float  g_bufB[(size_t)NMAX * DD];   // agg target (fp32)
__device__ __align__(16) __half g_scaled[(size_t)NMAX * DD]; // rs_out-scaled gather rows (fp16)
__device__ __align__(16) float  g_token[DD];
__device__ int   g_deg_out[NMAX];
__device__ int   g_deg_in[NMAX];
__device__ float g_rs_out[NMAX];
__device__ float g_rs_in[NMAX];
__device__ int   g_maskflag[NMAX];
__device__ int   g_rowptr[NMAX + 1];
__device__ int   g_fill[NMAX];
__device__ int   g_csrc[EMAX];      // CSR (by dst) source-node list

// ---------------- small setup kernels ----------------
__global__ void k_copy(const float* __restrict__ src, float* __restrict__ dst, int n) {
    int i = blockIdx.x * blockDim.x + threadIdx.x;
    if (i < n) dst[i] = src[i];
}

__global__ void k_init(int* __restrict__ deg_out, int* __restrict__ deg_in,
                       int* __restrict__ fill, int* __restrict__ maskflag,
                       float* __restrict__ out, int n) {
    int i = blockIdx.x * blockDim.x + threadIdx.x;
    if (i < n) { deg_out[i] = 0; deg_in[i] = 0; fill[i] = 0; maskflag[i] = 0; }
    if (i == 0) out[0] = 0.f;
}

__global__ void k_mark(const int* __restrict__ mask_nodes, int* __restrict__ maskflag, int m) {
    int i = blockIdx.x * blockDim.x + threadIdx.x;
    if (i < m) maskflag[mask_nodes[i]] = 1;
}

__global__ void k_deg(const int* __restrict__ src, const int* __restrict__ dst,
                      int* __restrict__ dout, int* __restrict__ din, int e) {
    int i = blockIdx.x * blockDim.x + threadIdx.x;
    if (i < e) {
        atomicAdd(&dout[src[i]], 1);
        atomicAdd(&din[dst[i]], 1);
    }
}

__global__ void k_rsqrt(const int* __restrict__ dout, const int* __restrict__ din,
                        float* __restrict__ ro, float* __restrict__ ri, int n) {
    int i = blockIdx.x * blockDim.x + threadIdx.x;
    if (i < n) {
        ro[i] = rsqrtf(fmaxf((float)dout[i], 1.f));
        ri[i] = rsqrtf(fmaxf((float)din[i], 1.f));
    }
}

// ---------------- exclusive scan of in-degrees -> rowptr (single block) ----------------
__global__ void __launch_bounds__(1024)
k_scan(const int* __restrict__ deg, int* __restrict__ rowptr, int n) {
    __shared__ int part[1024];
    int t = threadIdx.x;
    int chunk = (n + 1023) / 1024;
    int lo = t * chunk;
    int hi = lo + chunk; if (hi > n) hi = n; if (lo > n) lo = n;
    int s = 0;
    for (int i = lo; i < hi; i++) s += deg[i];
    part[t] = s;
    __syncthreads();
    for (int o = 1; o < 1024; o <<= 1) {
        int v = (t >= o) ? part[t - o] : 0;
        __syncthreads();
        part[t] += v;
        __syncthreads();
    }
    int base = (t == 0) ? 0 : part[t - 1];
    for (int i = lo; i < hi; i++) {
        rowptr[i] = base;
        base += deg[i];
    }
    if (t == 1023) rowptr[n] = part[1023];
}

__global__ void k_fill(const int* __restrict__ src, const int* __restrict__ dst,
                       const int* __restrict__ rowptr, int* __restrict__ fill,
                       int* __restrict__ csrc, int e) {
    int i = blockIdx.x * blockDim.x + threadIdx.x;
    if (i < e) {
        int d = dst[i];
        int p = rowptr[d] + atomicAdd(&fill[d], 1);
        csrc[p] = src[i];
    }
}

// ---------------- prep for conv1: scaled[v] = (mask? token : x[v]) * rs_out[v] as fp16 ----
// warp per node; lane handles 4 floats. x is EXTERNAL: scalar coalesced loads.
__global__ void __launch_bounds__(256)
k_prep1(const float* __restrict__ x, const float* __restrict__ token,
        const int* __restrict__ maskflag, const float* __restrict__ rs_out,
        __half* __restrict__ scaled, int n) {
    int w = (blockIdx.x * blockDim.x + threadIdx.x) >> 5;
    int lane = threadIdx.x & 31;
    if (w >= n) return;
    float r = rs_out[w];
    const float* srcp = maskflag[w] ? (token + lane * 4) : (x + (size_t)w * DD + lane * 4);
    float v0 = srcp[0] * r, v1 = srcp[1] * r, v2 = srcp[2] * r, v3 = srcp[3] * r;
    __half2 p0 = __floats2half2_rn(v0, v1);
    __half2 p1 = __floats2half2_rn(v2, v3);
    uint2 u;
    *(__half2*)&u.x = p0;
    *(__half2*)&u.y = p1;
    ((uint2*)scaled)[(size_t)w * 32 + lane] = u;
}

// ---------------- CSR aggregation over fp16 scaled rows ----------------
// one warp per node; lane owns 4 halfs (8B) of the 256B row; fp32 accumulate; no atomics.
__global__ void __launch_bounds__(256)
k_agg(const __half* __restrict__ scaled,
      const int* __restrict__ rowptr, const int* __restrict__ csrc,
      float* __restrict__ agg, int n) {
    int w = (blockIdx.x * blockDim.x + threadIdx.x) >> 5;
    int lane = threadIdx.x & 31;
    if (w >= n) return;
    int beg = rowptr[w];
    int end = rowptr[w + 1];
    float4 acc = make_float4(0.f, 0.f, 0.f, 0.f);
    for (int e = beg; e < end; e++) {
        int s = csrc[e];                               // warp-broadcast
        uint2 u = ((const uint2*)scaled)[(size_t)s * 32 + lane];
        float2 f0 = __half22float2(*(__half2*)&u.x);
        float2 f1 = __half22float2(*(__half2*)&u.y);
        acc.x += f0.x; acc.y += f0.y; acc.z += f1.x; acc.w += f1.y;
    }
    ((float4*)agg)[(size_t)w * 32 + lane] = acc;
}

// ---------------- fused GEMM (out = in @ W^T [+ bias]) + epilogue ----------------
// mode 0: (in@W^T + b)*rs_in -> LayerNorm -> PReLU    (encoder layers)
// mode 1: (in@W^T + b)*rs_in                           (decoder conv, fp32 out)
// mode 2: in@W^T, zero masked rows                     (enc->dec re-mask)
// half_out: write fp16 rows scaled by rs_out (for next aggregation) instead of fp32.
__global__ void __launch_bounds__(512, 2)
k_gemm(const float* __restrict__ in, float* __restrict__ out, __half* __restrict__ out_h,
       const float* __restrict__ W, const float* __restrict__ bias,
       const float* __restrict__ rs_in, const float* __restrict__ rs_out,
       const float* __restrict__ gamma, const float* __restrict__ beta,
       const float* __restrict__ alpha,
       const int* __restrict__ maskflag,
       int n, int mode, int half_out) {
    extern __shared__ float sm[];
    float* sW = sm;                 // [128][SWS] transposed W
    float* sA = sm + 128 * SWS;     // [64][128] input tile

    const int tid  = threadIdx.x;
    const int row0 = blockIdx.x * 64;

    #pragma unroll
    for (int i = tid; i < 128 * 128; i += 512) {
        int c = i >> 7;
        int k = i & 127;
        sW[k * SWS + c] = W[i];     // scalar coalesced (external W)
    }
    int rows = n - row0; if (rows > 64) rows = 64;
    #pragma unroll
    for (int i = tid; i < 64 * 32; i += 512) {
        int r = i >> 5, c4 = i & 31;
        float4 v = (r < rows) ? ((const float4*)in)[(size_t)(row0 + r) * 32 + c4]
                              : make_float4(0.f, 0.f, 0.f, 0.f);
        ((float4*)sA)[i] = v;
    }
    __syncthreads();

    const int tx = tid & 31;
    const int ty = tid >> 5;
    const int c0 = tx * 4;
    const int r0 = ty * 4;

    float acc[4][4];
    #pragma unroll
    for (int i = 0; i < 4; i++)
        #pragma unroll
        for (int j = 0; j < 4; j++) acc[i][j] = 0.f;

    #pragma unroll 8
    for (int k = 0; k < 128; k++) {
        float4 w = *(const float4*)&sW[k * SWS + c0];   // 16B-aligned (SWS%4==0)
        float a0 = sA[(r0 + 0) * 128 + k];
        float a1 = sA[(r0 + 1) * 128 + k];
        float a2 = sA[(r0 + 2) * 128 + k];
        float a3 = sA[(r0 + 3) * 128 + k];
        acc[0][0] += a0 * w.x; acc[0][1] += a0 * w.y; acc[0][2] += a0 * w.z; acc[0][3] += a0 * w.w;
        acc[1][0] += a1 * w.x; acc[1][1] += a1 * w.y; acc[1][2] += a1 * w.z; acc[1][3] += a1 * w.w;
        acc[2][0] += a2 * w.x; acc[2][1] += a2 * w.y; acc[2][2] += a2 * w.z; acc[2][3] += a2 * w.w;
        acc[3][0] += a3 * w.x; acc[3][1] += a3 * w.y; acc[3][2] += a3 * w.z; acc[3][3] += a3 * w.w;
    }

    float aP = (mode == 0) ? alpha[0] : 0.f;
    float b0 = 0.f, b1v = 0.f, b2v = 0.f, b3 = 0.f;
    float gx = 0.f, gy = 0.f, gz = 0.f, gw_ = 0.f;
    float ex = 0.f, ey = 0.f, ez = 0.f, ew = 0.f;
    if (mode != 2) {
        b0 = bias[c0 + 0]; b1v = bias[c0 + 1]; b2v = bias[c0 + 2]; b3 = bias[c0 + 3];
    }
    if (mode == 0) {
        gx = gamma[c0 + 0]; gy = gamma[c0 + 1]; gz = gamma[c0 + 2]; gw_ = gamma[c0 + 3];
        ex = beta[c0 + 0];  ey = beta[c0 + 1];  ez = beta[c0 + 2];  ew = beta[c0 + 3];
    }
    #pragma unroll
    for (int i = 0; i < 4; i++) {
        int row = row0 + r0 + i;
        if (row >= n) continue;
        float y0, y1, y2, y3;
        if (mode == 2) {
            if (maskflag[row]) { y0 = y1 = y2 = y3 = 0.f; }
            else { y0 = acc[i][0]; y1 = acc[i][1]; y2 = acc[i][2]; y3 = acc[i][3]; }
        } else {
            float rs = rs_in[row];
            float v0 = (acc[i][0] + b0)  * rs;
            float v1 = (acc[i][1] + b1v) * rs;
            float v2 = (acc[i][2] + b2v) * rs;
            float v3 = (acc[i][3] + b3)  * rs;
            if (mode == 0) {
                float s  = v0 + v1 + v2 + v3;
                float ss = v0 * v0 + v1 * v1 + v2 * v2 + v3 * v3;
                #pragma unroll
                for (int o = 16; o; o >>= 1) {
                    s  += __shfl_xor_sync(0xffffffffu, s,  o);
                    ss += __shfl_xor_sync(0xffffffffu, ss, o);
                }
                float mu  = s * (1.f / 128.f);
                float var = ss * (1.f / 128.f) - mu * mu;
                float inv = rsqrtf(var + 1e-5f);
                y0 = (v0 - mu) * inv * gx  + ex; y0 = (y0 >= 0.f) ? y0 : aP * y0;
                y1 = (v1 - mu) * inv * gy  + ey; y1 = (y1 >= 0.f) ? y1 : aP * y1;
                y2 = (v2 - mu) * inv * gz  + ez; y2 = (y2 >= 0.f) ? y2 : aP * y2;
                y3 = (v3 - mu) * inv * gw_ + ew; y3 = (y3 >= 0.f) ? y3 : aP * y3;
            } else {
                y0 = v0; y1 = v1; y2 = v2; y3 = v3;
            }
        }
        if (half_out) {
            float rso = rs_out[row];
            __half2 p0 = __floats2half2_rn(y0 * rso, y1 * rso);
            __half2 p1 = __floats2half2_rn(y2 * rso, y3 * rso);
            uint2 u;
            *(__half2*)&u.x = p0;
            *(__half2*)&u.y = p1;
            ((uint2*)out_h)[(size_t)row * 32 + tx] = u;
        } else {
            ((float4*)out)[(size_t)row * 32 + tx] = make_float4(y0, y1, y2, y3);
        }
    }
}

// ---------------- SCE loss over masked rows ----------------
// recon is OUR buffer; x is EXTERNAL (scalar coalesced loads).
__global__ void __launch_bounds__(256)
k_loss(const float* __restrict__ recon, const float* __restrict__ x,
       const int* __restrict__ mask_nodes, int m, float* __restrict__ out) {
    __shared__ float part[8];
    int gw   = (blockIdx.x * blockDim.x + threadIdx.x) >> 5;
    int lane = threadIdx.x & 31;
    int wl   = threadIdx.x >> 5;
    float term = 0.f;
    if (gw < m) {
        int node = mask_nodes[gw];
        float4 r = ((const float4*)recon)[(size_t)node * 32 + lane];
        const float* xp = x + (size_t)node * DD + lane * 4;
        float x0 = xp[0], x1 = xp[1], x2 = xp[2], x3 = xp[3];
        float dot = r.x * x0 + r.y * x1 + r.z * x2 + r.w * x3;
        float nr  = r.x * r.x + r.y * r.y + r.z * r.z + r.w * r.w;
        float nx  = x0 * x0 + x1 * x1 + x2 * x2 + x3 * x3;
        #pragma unroll
        for (int o = 16; o; o >>= 1) {
            dot += __shfl_xor_sync(0xffffffffu, dot, o);
            nr  += __shfl_xor_sync(0xffffffffu, nr,  o);
            nx  += __shfl_xor_sync(0xffffffffu, nx,  o);
        }
        if (lane == 0) {
            float c = dot / (fmaxf(sqrtf(nr), 1e-12f) * fmaxf(sqrtf(nx), 1e-12f));
            float t = 1.f - c;
            term = t * t;
        }
    }
    if (lane == 0) part[wl] = term;
    __syncthreads();
    if (threadIdx.x == 0) {
        float s = 0.f;
        #pragma unroll
        for (int i = 0; i < 8; i++) s += part[i];
        atomicAdd(out, s / (float)m);
    }
}

// ---------------- launch ----------------
extern "C" void kernel_launch(void* const* d_in, const int* in_sizes, int n_in,
                              void* d_out, int out_size) {
    const float* x     = (const float*)d_in[0];
    const float* token = (const float*)d_in[1];
    const float* W1    = (const float*)d_in[2];
    const float* b1    = (const float*)d_in[3];
    const float* g1    = (const float*)d_in[4];
    const float* be1   = (const float*)d_in[5];
    const float* a1    = (const float*)d_in[6];
    const float* W2    = (const float*)d_in[7];
    const float* b2    = (const float*)d_in[8];
    const float* g2    = (const float*)d_in[9];
    const float* be2   = (const float*)d_in[10];
    const float* a2    = (const float*)d_in[11];
    const float* We2d  = (const float*)d_in[12];
    const float* Wd    = (const float*)d_in[13];
    const float* bd    = (const float*)d_in[14];
    const int*   src   = (const int*)d_in[15];
    const int*   dst   = (const int*)d_in[16];
    const int*   mask  = (const int*)d_in[17];

    const int n = in_sizes[0] / DD;
    const int E = in_sizes[15];
    const int M = in_sizes[17];
    float* out = (float*)d_out;

    float *bufA, *bufB, *tokA, *rs_out, *rs_in;
    __half* scaled;
    int *deg_out, *deg_in, *maskflag, *rowptr, *fill, *csrc;
    cudaGetSymbolAddress((void**)&bufA, g_bufA);
    cudaGetSymbolAddress((void**)&bufB, g_bufB);
    cudaGetSymbolAddress((void**)&scaled, g_scaled);
    cudaGetSymbolAddress((void**)&tokA, g_token);
    cudaGetSymbolAddress((void**)&deg_out, g_deg_out);
    cudaGetSymbolAddress((void**)&deg_in,  g_deg_in);
    cudaGetSymbolAddress((void**)&rs_out, g_rs_out);
    cudaGetSymbolAddress((void**)&rs_in,  g_rs_in);
    cudaGetSymbolAddress((void**)&maskflag, g_maskflag);
    cudaGetSymbolAddress((void**)&rowptr, g_rowptr);
    cudaGetSymbolAddress((void**)&fill,   g_fill);
    cudaGetSymbolAddress((void**)&csrc,   g_csrc);

    const size_t smem = (128 * SWS + 64 * 128) * sizeof(float);   // 100352 B
    cudaFuncSetAttribute(k_gemm, cudaFuncAttributeMaxDynamicSharedMemorySize, (int)smem);

    const int T = 256;
    const int gN = (n + T - 1) / T;
    const int gE = (E + T - 1) / T;
    const int gW = ((n * 32) + T - 1) / T;          // warp-per-node kernels
    const int gG = (n + 63) / 64;
    const int gL = ((M * 32) + T - 1) / T;

    // setup: degrees, mask flags, rsqrt norms, CSR build
    k_copy <<<1, DD>>>(token, tokA, DD);
    k_init <<<gN, T>>>(deg_out, deg_in, fill, maskflag, out, n);
    k_mark <<<(M + T - 1) / T, T>>>(mask, maskflag, M);
    k_deg  <<<gE, T>>>(src, dst, deg_out, deg_in, E);
    k_rsqrt<<<gN, T>>>(deg_out, deg_in, rs_out, rs_in, n);
    k_scan <<<1, 1024>>>(deg_in, rowptr, n);
    k_fill <<<gE, T>>>(src, dst, rowptr, fill, csrc, E);

    // ---- conv1: prep fp16 scaled(use_x) -> agg -> GEMM+LN+PReLU -> scaled (fp16, *rs_out)
    k_prep1<<<gW, T>>>(x, tokA, maskflag, rs_out, scaled, n);
    k_agg  <<<gW, T>>>(scaled, rowptr, csrc, bufB, n);
    k_gemm <<<gG, 512, smem>>>(bufB, nullptr, scaled, W1, b1, rs_in, rs_out, g1, be1, a1, maskflag, n, 0, 1);

    // ---- conv2: agg -> GEMM+LN+PReLU -> bufA (fp32, feeds enc->dec GEMM)
    k_agg  <<<gW, T>>>(scaled, rowptr, csrc, bufB, n);
    k_gemm <<<gG, 512, smem>>>(bufB, bufA, nullptr, W2, b2, rs_in, rs_out, g2, be2, a2, maskflag, n, 0, 0);

    // ---- encoder_to_decoder + re-mask -> scaled (fp16, *rs_out)
    k_gemm <<<gG, 512, smem>>>(bufA, nullptr, scaled, We2d, bd, rs_in, rs_out, g2, be2, a2, maskflag, n, 2, 1);

    // ---- decoder conv: agg -> GEMM (bias + deg scale) -> bufA = recon (fp32)
    k_agg  <<<gW, T>>>(scaled, rowptr, csrc, bufB, n);
    k_gemm <<<gG, 512, smem>>>(bufB, bufA, nullptr, Wd, bd, rs_in, rs_out, g2, be2, a2, maskflag, n, 1, 0);

    // ---- SCE loss on masked rows
    k_loss <<<gL, T>>>(bufA, x, mask, M, out);
}

// round 7
// speedup vs baseline: 2.4842x; 1.7798x over previous
#include <cuda_runtime.h>
#include <cuda_fp16.h>
#include <cstdint>
#include <stdint.h>
#include <math.h>

#define DD 128
#define NMAX 50000
#define EMAX 800000
#define SROW 136            // smem row stride in halfs (272B, 16B-multiple)

// ---------------- scratch (static device globals) ----------------
__device__ __align__(16) float  g_recon[(size_t)NMAX * DD];   // recon (fp32, loss input)
__device__ __align__(16) __half g_S[(size_t)NMAX * DD];       // rs_out-scaled gather rows
__device__ __align__(16) __half g_agg16[(size_t)NMAX * DD];   // aggregation output (fp16)
__device__ __align__(16) __half g_h2[(size_t)NMAX * DD];      // encoder layer-2 output
__device__ __align__(16) float  g_token[DD];
__device__ int   g_deg_out[NMAX];
__device__ int   g_deg_in[NMAX];
__device__ float g_rs_out[NMAX];
__device__ float g_rs_in[NMAX];
__device__ int   g_maskflag[NMAX];
__device__ int   g_rowptr[NMAX + 1];
__device__ int   g_fill[NMAX];
__device__ int   g_csrc[EMAX];

// ---------------- small setup kernels ----------------
__global__ void k_copy(const float* __restrict__ src, float* __restrict__ dst, int n) {
    int i = blockIdx.x * blockDim.x + threadIdx.x;
    if (i < n) dst[i] = src[i];
}

__global__ void k_init(int* __restrict__ deg_out, int* __restrict__ deg_in,
                       int* __restrict__ fill, int* __restrict__ maskflag,
                       float* __restrict__ out, int n) {
    int i = blockIdx.x * blockDim.x + threadIdx.x;
    if (i < n) { deg_out[i] = 0; deg_in[i] = 0; fill[i] = 0; maskflag[i] = 0; }
    if (i == 0) out[0] = 0.f;
}

__global__ void k_mark(const int* __restrict__ mask_nodes, int* __restrict__ maskflag, int m) {
    int i = blockIdx.x * blockDim.x + threadIdx.x;
    if (i < m) maskflag[mask_nodes[i]] = 1;
}

__global__ void k_deg(const int* __restrict__ src, const int* __restrict__ dst,
                      int* __restrict__ dout, int* __restrict__ din, int e) {
    int i = blockIdx.x * blockDim.x + threadIdx.x;
    if (i < e) {
        atomicAdd(&dout[src[i]], 1);
        atomicAdd(&din[dst[i]], 1);
    }
}

__global__ void k_rsqrt(const int* __restrict__ dout, const int* __restrict__ din,
                        float* __restrict__ ro, float* __restrict__ ri, int n) {
    int i = blockIdx.x * blockDim.x + threadIdx.x;
    if (i < n) {
        ro[i] = rsqrtf(fmaxf((float)dout[i], 1.f));
        ri[i] = rsqrtf(fmaxf((float)din[i], 1.f));
    }
}

__global__ void __launch_bounds__(1024)
k_scan(const int* __restrict__ deg, int* __restrict__ rowptr, int n) {
    __shared__ int part[1024];
    int t = threadIdx.x;
    int chunk = (n + 1023) / 1024;
    int lo = t * chunk;
    int hi = lo + chunk; if (hi > n) hi = n; if (lo > n) lo = n;
    int s = 0;
    for (int i = lo; i < hi; i++) s += deg[i];
    part[t] = s;
    __syncthreads();
    for (int o = 1; o < 1024; o <<= 1) {
        int v = (t >= o) ? part[t - o] : 0;
        __syncthreads();
        part[t] += v;
        __syncthreads();
    }
    int base = (t == 0) ? 0 : part[t - 1];
    for (int i = lo; i < hi; i++) {
        rowptr[i] = base;
        base += deg[i];
    }
    if (t == 1023) rowptr[n] = part[1023];
}

__global__ void k_fill(const int* __restrict__ src, const int* __restrict__ dst,
                       const int* __restrict__ rowptr, int* __restrict__ fill,
                       int* __restrict__ csrc, int e) {
    int i = blockIdx.x * blockDim.x + threadIdx.x;
    if (i < e) {
        int d = dst[i];
        int p = rowptr[d] + atomicAdd(&fill[d], 1);
        csrc[p] = src[i];
    }
}

// ---------------- prep: S[v] = (mask? token : x[v]) * rs_out[v] fp16 ----------------
__global__ void __launch_bounds__(256)
k_prep1(const float* __restrict__ x, const float* __restrict__ token,
        const int* __restrict__ maskflag, const float* __restrict__ rs_out,
        __half* __restrict__ S, int n) {
    int w = (blockIdx.x * blockDim.x + threadIdx.x) >> 5;
    int lane = threadIdx.x & 31;
    if (w >= n) return;
    float r = rs_out[w];
    const float* srcp = maskflag[w] ? (token + lane * 4) : (x + (size_t)w * DD + lane * 4);
    __half2 p0 = __floats2half2_rn(srcp[0] * r, srcp[1] * r);
    __half2 p1 = __floats2half2_rn(srcp[2] * r, srcp[3] * r);
    uint2 u;
    *(__half2*)&u.x = p0;
    *(__half2*)&u.y = p1;
    ((uint2*)S)[(size_t)w * 32 + lane] = u;
}

// ---------------- CSR aggregation (fp16 in, fp32 accum, fp16 out) ----------------
__global__ void __launch_bounds__(256)
k_agg(const __half* __restrict__ S,
      const int* __restrict__ rowptr, const int* __restrict__ csrc,
      __half* __restrict__ agg, int n) {
    int w = (blockIdx.x * blockDim.x + threadIdx.x) >> 5;
    int lane = threadIdx.x & 31;
    if (w >= n) return;
    int beg = rowptr[w];
    int end = rowptr[w + 1];
    float4 acc = make_float4(0.f, 0.f, 0.f, 0.f);
    for (int e = beg; e < end; e++) {
        int s = csrc[e];
        uint2 u = ((const uint2*)S)[(size_t)s * 32 + lane];
        float2 f0 = __half22float2(*(__half2*)&u.x);
        float2 f1 = __half22float2(*(__half2*)&u.y);
        acc.x += f0.x; acc.y += f0.y; acc.z += f1.x; acc.w += f1.y;
    }
    uint2 o;
    *(__half2*)&o.x = __floats2half2_rn(acc.x, acc.y);
    *(__half2*)&o.y = __floats2half2_rn(acc.z, acc.w);
    ((uint2*)agg)[(size_t)w * 32 + lane] = o;
}

// ---------------- tensor-core GEMM: out = in(fp16) @ W^T + epilogue ----------------
// mode 0: (acc+b)*rs_in -> LN -> PReLU -> fp16 (optionally *rs_out)   [encoder layers]
// mode 1: (acc+b)*rs_in -> fp32                                        [decoder conv]
// mode 2: acc, re-mask, *rs_out (=1 here) -> fp16                      [enc->dec]
__global__ void __launch_bounds__(256, 2)
k_gemm(const __half* __restrict__ in, __half* __restrict__ outh, float* __restrict__ outf,
       const float* __restrict__ W, const float* __restrict__ bias,
       const float* __restrict__ rs_in, const float* __restrict__ rs_out,
       const float* __restrict__ gamma, const float* __restrict__ beta,
       const float* __restrict__ alpha,
       const int* __restrict__ maskflag,
       int n, int mode, int scale_rso) {
    extern __shared__ char smraw[];
    __half* sA = (__half*)smraw;                    // [128][SROW]
    __half* sW = sA + 128 * SROW;                   // [128][SROW]
    float* sBias  = (float*)(sW + 128 * SROW);      // [128]
    float* sGamma = sBias + 128;                    // [128]
    float* sBeta  = sGamma + 128;                   // [128]

    const int tid  = threadIdx.x;
    const int row0 = blockIdx.x * 128;

    // ---- stage A tile ----
    #pragma unroll
    for (int it = 0; it < 16; it++) {
        int idx = it * 256 + tid;                   // 0..4095
        int r = idx >> 5, c4 = idx & 31;
        uint2 v = make_uint2(0u, 0u);
        int gr = row0 + r;
        if (gr < n) v = ((const uint2*)in)[(size_t)gr * 32 + c4];
        *(uint2*)&sA[r * SROW + c4 * 4] = v;
    }
    // ---- stage W tile (external fp32 -> fp16) ----
    #pragma unroll
    for (int it = 0; it < 32; it++) {
        int idx = it * 256 + tid;                   // pair index 0..8191
        int base2 = idx * 2;
        int cc = base2 >> 7, kk = base2 & 127;
        float w0 = W[base2], w1 = W[base2 + 1];
        *(__half2*)&sW[cc * SROW + kk] = __floats2half2_rn(w0, w1);
    }
    if (tid < 128) {
        sBias[tid]  = (mode != 2) ? bias[tid] : 0.f;
        sGamma[tid] = (mode == 0) ? gamma[tid] : 0.f;
        sBeta[tid]  = (mode == 0) ? beta[tid] : 0.f;
    }
    __syncthreads();

    const int warp = tid >> 5;
    const int lane = tid & 31;

    float c[16][4];
    #pragma unroll
    for (int i = 0; i < 16; i++) {
        c[i][0] = 0.f; c[i][1] = 0.f; c[i][2] = 0.f; c[i][3] = 0.f;
    }

    uint32_t sAu = (uint32_t)__cvta_generic_to_shared(sA);
    uint32_t sWu = (uint32_t)__cvta_generic_to_shared(sW);
    uint32_t aBase = sAu + (uint32_t)((warp * 16 + (lane & 15)) * (SROW * 2) + (lane >> 4) * 16);
    uint32_t bRow  = (uint32_t)((lane >> 4) * 8 + (lane & 7));
    uint32_t bKoff = (uint32_t)(((lane >> 3) & 1) * 16);

    #pragma unroll
    for (int kb = 0; kb < 8; kb++) {
        uint32_t a0, a1, a2, a3;
        asm volatile("ldmatrix.sync.aligned.m8n8.x4.shared.b16 {%0,%1,%2,%3}, [%4];"
                     : "=r"(a0), "=r"(a1), "=r"(a2), "=r"(a3)
                     : "r"(aBase + kb * 32));
        #pragma unroll
        for (int ng = 0; ng < 8; ng++) {
            uint32_t b0, b1, b2, b3;
            uint32_t baddr = sWu + (uint32_t)((ng * 16 + bRow) * (SROW * 2) + kb * 32 + bKoff);
            asm volatile("ldmatrix.sync.aligned.m8n8.x4.shared.b16 {%0,%1,%2,%3}, [%4];"
                         : "=r"(b0), "=r"(b1), "=r"(b2), "=r"(b3)
                         : "r"(baddr));
            int t0 = ng * 2, t1 = ng * 2 + 1;
            asm volatile("mma.sync.aligned.m16n8k16.row.col.f32.f16.f16.f32 "
                         "{%0,%1,%2,%3}, {%4,%5,%6,%7}, {%8,%9}, {%0,%1,%2,%3};"
                         : "+f"(c[t0][0]), "+f"(c[t0][1]), "+f"(c[t0][2]), "+f"(c[t0][3])
                         : "r"(a0), "r"(a1), "r"(a2), "r"(a3), "r"(b0), "r"(b1));
            asm volatile("mma.sync.aligned.m16n8k16.row.col.f32.f16.f16.f32 "
                         "{%0,%1,%2,%3}, {%4,%5,%6,%7}, {%8,%9}, {%0,%1,%2,%3};"
                         : "+f"(c[t1][0]), "+f"(c[t1][1]), "+f"(c[t1][2]), "+f"(c[t1][3])
                         : "r"(a0), "r"(a1), "r"(a2), "r"(a3), "r"(b2), "r"(b3));
        }
    }

    // ---- epilogue ----
    int r0 = row0 + warp * 16 + (lane >> 2);
    int r1 = r0 + 8;
    int q  = lane & 3;

    if (mode == 2) {
        float rso0 = (r0 < n) ? ((maskflag[r0]) ? 0.f : (scale_rso ? rs_out[r0] : 1.f)) : 0.f;
        float rso1 = (r1 < n) ? ((maskflag[r1]) ? 0.f : (scale_rso ? rs_out[r1] : 1.f)) : 0.f;
        #pragma unroll
        for (int ct = 0; ct < 16; ct++) {
            int ci = ct * 4 + q;
            if (r0 < n) ((__half2*)outh)[(size_t)r0 * 64 + ci] = __floats2half2_rn(c[ct][0] * rso0, c[ct][1] * rso0);
            if (r1 < n) ((__half2*)outh)[(size_t)r1 * 64 + ci] = __floats2half2_rn(c[ct][2] * rso1, c[ct][3] * rso1);
        }
        return;
    }

    float rsi0 = (r0 < n) ? rs_in[r0] : 1.f;
    float rsi1 = (r1 < n) ? rs_in[r1] : 1.f;
    #pragma unroll
    for (int ct = 0; ct < 16; ct++) {
        int colb = ct * 8 + q * 2;
        float bb0 = sBias[colb], bb1 = sBias[colb + 1];
        c[ct][0] = (c[ct][0] + bb0) * rsi0;
        c[ct][1] = (c[ct][1] + bb1) * rsi0;
        c[ct][2] = (c[ct][2] + bb0) * rsi1;
        c[ct][3] = (c[ct][3] + bb1) * rsi1;
    }

    if (mode == 1) {
        #pragma unroll
        for (int ct = 0; ct < 16; ct++) {
            int ci = ct * 4 + q;
            if (r0 < n) ((float2*)outf)[(size_t)r0 * 64 + ci] = make_float2(c[ct][0], c[ct][1]);
            if (r1 < n) ((float2*)outf)[(size_t)r1 * 64 + ci] = make_float2(c[ct][2], c[ct][3]);
        }
        return;
    }

    // mode 0: LayerNorm (quad reduction) + PReLU
    float s0 = 0.f, ss0 = 0.f, s1 = 0.f, ss1 = 0.f;
    #pragma unroll
    for (int ct = 0; ct < 16; ct++) {
        s0  += c[ct][0] + c[ct][1];
        ss0 += c[ct][0] * c[ct][0] + c[ct][1] * c[ct][1];
        s1  += c[ct][2] + c[ct][3];
        ss1 += c[ct][2] * c[ct][2] + c[ct][3] * c[ct][3];
    }
    #pragma unroll
    for (int o = 1; o <= 2; o <<= 1) {
        s0  += __shfl_xor_sync(0xffffffffu, s0,  o);
        ss0 += __shfl_xor_sync(0xffffffffu, ss0, o);
        s1  += __shfl_xor_sync(0xffffffffu, s1,  o);
        ss1 += __shfl_xor_sync(0xffffffffu, ss1, o);
    }
    float mu0 = s0 * (1.f / 128.f);
    float mu1 = s1 * (1.f / 128.f);
    float inv0 = rsqrtf(ss0 * (1.f / 128.f) - mu0 * mu0 + 1e-5f);
    float inv1 = rsqrtf(ss1 * (1.f / 128.f) - mu1 * mu1 + 1e-5f);
    float aP = alpha[0];
    float rso0 = 1.f, rso1 = 1.f;
    if (scale_rso) {
        rso0 = (r0 < n) ? rs_out[r0] : 1.f;
        rso1 = (r1 < n) ? rs_out[r1] : 1.f;
    }
    #pragma unroll
    for (int ct = 0; ct < 16; ct++) {
        int colb = ct * 8 + q * 2;
        float g0 = sGamma[colb], g1 = sGamma[colb + 1];
        float e0 = sBeta[colb],  e1 = sBeta[colb + 1];
        float y0 = (c[ct][0] - mu0) * inv0 * g0 + e0; y0 = (y0 >= 0.f) ? y0 : aP * y0;
        float y1 = (c[ct][1] - mu0) * inv0 * g1 + e1; y1 = (y1 >= 0.f) ? y1 : aP * y1;
        float y2 = (c[ct][2] - mu1) * inv1 * g0 + e0; y2 = (y2 >= 0.f) ? y2 : aP * y2;
        float y3 = (c[ct][3] - mu1) * inv1 * g1 + e1; y3 = (y3 >= 0.f) ? y3 : aP * y3;
        int ci = ct * 4 + q;
        if (r0 < n) ((__half2*)outh)[(size_t)r0 * 64 + ci] = __floats2half2_rn(y0 * rso0, y1 * rso0);
        if (r1 < n) ((__half2*)outh)[(size_t)r1 * 64 + ci] = __floats2half2_rn(y2 * rso1, y3 * rso1);
    }
}

// ---------------- SCE loss over masked rows ----------------
__global__ void __launch_bounds__(256)
k_loss(const float* __restrict__ recon, const float* __restrict__ x,
       const int* __restrict__ mask_nodes, int m, float* __restrict__ out) {
    __shared__ float part[8];
    int gw   = (blockIdx.x * blockDim.x + threadIdx.x) >> 5;
    int lane = threadIdx.x & 31;
    int wl   = threadIdx.x >> 5;
    float term = 0.f;
    if (gw < m) {
        int node = mask_nodes[gw];
        float4 r = ((const float4*)recon)[(size_t)node * 32 + lane];
        const float* xp = x + (size_t)node * DD + lane * 4;
        float x0 = xp[0], x1 = xp[1], x2 = xp[2], x3 = xp[3];
        float dot = r.x * x0 + r.y * x1 + r.z * x2 + r.w * x3;
        float nr  = r.x * r.x + r.y * r.y + r.z * r.z + r.w * r.w;
        float nx  = x0 * x0 + x1 * x1 + x2 * x2 + x3 * x3;
        #pragma unroll
        for (int o = 16; o; o >>= 1) {
            dot += __shfl_xor_sync(0xffffffffu, dot, o);
            nr  += __shfl_xor_sync(0xffffffffu, nr,  o);
            nx  += __shfl_xor_sync(0xffffffffu, nx,  o);
        }
        if (lane == 0) {
            float cc = dot / (fmaxf(sqrtf(nr), 1e-12f) * fmaxf(sqrtf(nx), 1e-12f));
            float t = 1.f - cc;
            term = t * t;
        }
    }
    if (lane == 0) part[wl] = term;
    __syncthreads();
    if (threadIdx.x == 0) {
        float s = 0.f;
        #pragma unroll
        for (int i = 0; i < 8; i++) s += part[i];
        atomicAdd(out, s / (float)m);
    }
}

// ---------------- launch ----------------
extern "C" void kernel_launch(void* const* d_in, const int* in_sizes, int n_in,
                              void* d_out, int out_size) {
    const float* x     = (const float*)d_in[0];
    const float* token = (const float*)d_in[1];
    const float* W1    = (const float*)d_in[2];
    const float* b1    = (const float*)d_in[3];
    const float* g1    = (const float*)d_in[4];
    const float* be1   = (const float*)d_in[5];
    const float* a1    = (const float*)d_in[6];
    const float* W2    = (const float*)d_in[7];
    const float* b2    = (const float*)d_in[8];
    const float* g2    = (const float*)d_in[9];
    const float* be2   = (const float*)d_in[10];
    const float* a2    = (const float*)d_in[11];
    const float* We2d  = (const float*)d_in[12];
    const float* Wd    = (const float*)d_in[13];
    const float* bd    = (const float*)d_in[14];
    const int*   src   = (const int*)d_in[15];
    const int*   dst   = (const int*)d_in[16];
    const int*   mask  = (const int*)d_in[17];

    const int n = in_sizes[0] / DD;
    const int E = in_sizes[15];
    const int M = in_sizes[17];
    float* out = (float*)d_out;

    float *recon, *tokA, *rs_out, *rs_in;
    __half *S, *agg16, *h2;
    int *deg_out, *deg_in, *maskflag, *rowptr, *fill, *csrc;
    cudaGetSymbolAddress((void**)&recon, g_recon);
    cudaGetSymbolAddress((void**)&S,     g_S);
    cudaGetSymbolAddress((void**)&agg16, g_agg16);
    cudaGetSymbolAddress((void**)&h2,    g_h2);
    cudaGetSymbolAddress((void**)&tokA,  g_token);
    cudaGetSymbolAddress((void**)&deg_out, g_deg_out);
    cudaGetSymbolAddress((void**)&deg_in,  g_deg_in);
    cudaGetSymbolAddress((void**)&rs_out, g_rs_out);
    cudaGetSymbolAddress((void**)&rs_in,  g_rs_in);
    cudaGetSymbolAddress((void**)&maskflag, g_maskflag);
    cudaGetSymbolAddress((void**)&rowptr, g_rowptr);
    cudaGetSymbolAddress((void**)&fill,   g_fill);
    cudaGetSymbolAddress((void**)&csrc,   g_csrc);

    const size_t smem = (size_t)(2 * 128 * SROW) * sizeof(__half) + 3 * 128 * sizeof(float);
    cudaFuncSetAttribute(k_gemm, cudaFuncAttributeMaxDynamicSharedMemorySize, (int)smem);

    const int T = 256;
    const int gN = (n + T - 1) / T;
    const int gE = (E + T - 1) / T;
    const int gW = ((n * 32) + T - 1) / T;
    const int gG = (n + 127) / 128;
    const int gL = ((M * 32) + T - 1) / T;

    // setup
    k_copy <<<1, DD>>>(token, tokA, DD);
    k_init <<<gN, T>>>(deg_out, deg_in, fill, maskflag, out, n);
    k_mark <<<(M + T - 1) / T, T>>>(mask, maskflag, M);
    k_deg  <<<gE, T>>>(src, dst, deg_out, deg_in, E);
    k_rsqrt<<<gN, T>>>(deg_out, deg_in, rs_out, rs_in, n);
    k_scan <<<1, 1024>>>(deg_in, rowptr, n);
    k_fill <<<gE, T>>>(src, dst, rowptr, fill, csrc, E);

    // conv1: prep -> agg -> GEMM(LN+PReLU, *rs_out) -> S
    k_prep1<<<gW, T>>>(x, tokA, maskflag, rs_out, S, n);
    k_agg  <<<gW, T>>>(S, rowptr, csrc, agg16, n);
    k_gemm <<<gG, 256, smem>>>(agg16, S, nullptr, W1, b1, rs_in, rs_out, g1, be1, a1, maskflag, n, 0, 1);

    // conv2: agg -> GEMM(LN+PReLU) -> h2
    k_agg  <<<gW, T>>>(S, rowptr, csrc, agg16, n);
    k_gemm <<<gG, 256, smem>>>(agg16, h2, nullptr, W2, b2, rs_in, rs_out, g2, be2, a2, maskflag, n, 0, 0);

    // enc->dec + re-mask, *rs_out -> S
    k_gemm <<<gG, 256, smem>>>(h2, S, nullptr, We2d, bd, rs_in, rs_out, g2, be2, a2, maskflag, n, 2, 1);

    // decoder conv: agg -> GEMM(bias+rs_in) -> recon (fp32)
    k_agg  <<<gW, T>>>(S, rowptr, csrc, agg16, n);
    k_gemm <<<gG, 256, smem>>>(agg16, nullptr, recon, Wd, bd, rs_in, rs_out, g2, be2, a2, maskflag, n, 1, 0);

    // loss
    k_loss <<<gL, T>>>(recon, x, mask, M, out);
}